// round 5
// baseline (speedup 1.0000x reference)
#include <cuda_runtime.h>
#include <math.h>

constexpr int Nn  = 50000;
constexpr int Ee  = 800000;
constexpr int CIN = 16;
constexpr int CO  = 64;
constexpr int PB  = 196;     // preprocessing grid (all CTAs co-resident)
constexpr int SBK = 256;
constexpr int GR  = 64;      // GEMM rows per CTA

typedef unsigned long long ull;

// ---------------- device scratch ---------------------------------------------
__device__ int   g_is64;
__device__ float g_deg[Nn];
__device__ float g_dinv[Nn];
__device__ int   g_cnt[Nn];
__device__ int   g_rowptr[Nn + 1];
__device__ int   g_fill[Nn];
__device__ int   g_part[PB];
__device__ int   g_flagB[PB];
__device__ int   g_ph1, g_ph2;
__device__ int   g_csrc[Ee];
__device__ float g_cw[Ee];

__device__ float g_tx1[Nn * CIN];
__device__ float g_tx2[Nn * CIN];
__device__ float g_th1[Nn * CO];
__device__ float g_th2[Nn * CO];
__device__ float g_hr [Nn * CO];
__device__ float g_tr1[Nn * CO];
__device__ float g_tr2[Nn * CO];
__device__ float g_z  [Nn * CO];

// ---------------- small helpers ----------------------------------------------
__device__ __forceinline__ ull pack2(float lo, float hi) {
    ull r; asm("mov.b64 %0, {%1, %2};" : "=l"(r) : "f"(lo), "f"(hi)); return r;
}
__device__ __forceinline__ float2 unpack2(ull v) {
    float2 f; asm("mov.b64 {%0, %1}, %2;" : "=f"(f.x), "=f"(f.y) : "l"(v)); return f;
}
__device__ __forceinline__ void ffma2(ull& d, ull a, ull b) {
    asm("fma.rn.f32x2 %0, %1, %2, %0;" : "+l"(d) : "l"(a), "l"(b));
}
__device__ __forceinline__ float tanh_ap(float v) {
    float r; asm("tanh.approx.f32 %0, %1;" : "=f"(r) : "f"(v)); return r;
}
__device__ __forceinline__ float sigmoid_ap(float v) {
    return fmaf(tanh_ap(0.5f * v), 0.5f, 0.5f);
}

__device__ __forceinline__ void load_edge(const void* ei, int e, int& s, int& d) {
    if (g_is64) {
        const long long* p = (const long long*)ei;
        s = (int)p[e]; d = (int)p[Ee + e];
    } else {
        const int* p = (const int*)ei;
        s = p[e]; d = p[Ee + e];
    }
}

// ---------------- k_init: zero state + dtype detect ---------------------------
__global__ void k_init(const unsigned* __restrict__ ei_raw) {
    int i = blockIdx.x * blockDim.x + threadIdx.x;
    if (i < Nn) { g_deg[i] = 0.f; g_cnt[i] = 0; }
    if (i < PB) g_flagB[i] = 0;
    if (i == 0) { g_ph1 = 0; g_ph2 = 0; }
    if (blockIdx.x == 0) {
        if (threadIdx.x == 0) g_is64 = 1;
        __syncthreads();
        if (threadIdx.x < 256 && ei_raw[2 * threadIdx.x + 1] != 0u)
            atomicExch(&g_is64, 0);
    }
}

// ---------------- k_pre: degcnt + scan + dinv + fill + csr (one launch) -------
__global__ void k_pre(const void* __restrict__ ei, const float* __restrict__ ew) {
    int b = blockIdx.x, t = threadIdx.x;
    int tid = b * SBK + t;
    const int NT = PB * SBK;

    // phase A: degree + count
    for (int e = tid; e < Ee; e += NT) {
        int s, d; load_edge(ei, e, s, d);
        float w = ew[e];
        if (s != d) atomicAdd(&g_deg[s], w);
        atomicAdd(&g_cnt[d], 1);
    }
    __threadfence();
    __syncthreads();
    if (t == 0) {
        atomicAdd(&g_ph1, 1);
        while (*(volatile int*)&g_ph1 < PB) {}
    }
    __syncthreads();
    __threadfence();

    // phase B: block-local inclusive scan of cnt
    __shared__ int sm[SBK];
    int i = tid;
    int v = (i < Nn) ? g_cnt[i] : 0;
    sm[t] = v;
    __syncthreads();
#pragma unroll
    for (int off = 1; off < SBK; off <<= 1) {
        int u = (t >= off) ? sm[t - off] : 0;
        __syncthreads();
        sm[t] += u;
        __syncthreads();
    }
    int incl = sm[t];
    if (t == SBK - 1) {
        g_part[b] = incl;
        __threadfence();
        atomicExch(&g_flagB[b], 1);
    }
    // parallel lookback: thread j (< b) waits on block j's partial
    int pv = 0;
    if (t < b) {
        while (*(volatile int*)&g_flagB[t] == 0) {}
        pv = g_part[t];
    }
    __syncthreads();
    sm[t] = pv;
    __syncthreads();
#pragma unroll
    for (int off = SBK / 2; off > 0; off >>= 1) {
        if (t < off) sm[t] += sm[t + off];
        __syncthreads();
    }
    int prefix = sm[0];
    int inclg = incl + prefix;
    if (i < Nn) {
        g_rowptr[i + 1] = inclg;
        g_fill[i] = inclg - v;
        float dg = g_deg[i];
        g_dinv[i] = (dg > 0.f) ? rsqrtf(dg) : 0.f;
        if (i == 0) g_rowptr[0] = 0;
    }
    __threadfence();
    __syncthreads();
    if (t == 0) {
        atomicAdd(&g_ph2, 1);
        while (*(volatile int*)&g_ph2 < PB) {}
    }
    __syncthreads();
    __threadfence();

    // phase C: CSR scatter with normalized weights
    for (int e = tid; e < Ee; e += NT) {
        int s, d; load_edge(ei, e, s, d);
        float w  = ew[e];
        float wz = (s == d) ? 0.f : w;
        float nw = -g_dinv[s] * wz * g_dinv[d];
        int pos = atomicAdd(&g_fill[d], 1);
        g_csrc[pos] = s;
        g_cw[pos]   = nw;
    }
}

// ---------------- propagation (pull, CSR-by-dst) ------------------------------
__global__ void k_prop_xh1(const float* __restrict__ x, const float* __restrict__ h0) {
    int w = (blockIdx.x * blockDim.x + threadIdx.x) >> 5;
    if (w >= Nn) return;
    int lane = threadIdx.x & 31, cx = lane & 15;
    int beg = g_rowptr[w], end = g_rowptr[w + 1];
    float a0 = 0.f, a1 = 0.f, ax = 0.f;
    int e = beg;
    for (; e + 1 < end; e += 2) {
        int   s0 = g_csrc[e], s1 = g_csrc[e + 1];
        float w0 = g_cw[e],   w1 = g_cw[e + 1];
        a0 = fmaf(w0, h0[s0 * 64 + lane],      fmaf(w1, h0[s1 * 64 + lane],      a0));
        a1 = fmaf(w0, h0[s0 * 64 + 32 + lane], fmaf(w1, h0[s1 * 64 + 32 + lane], a1));
        ax = fmaf(w0, x [s0 * 16 + cx],        fmaf(w1, x [s1 * 16 + cx],        ax));
    }
    if (e < end) {
        int s = g_csrc[e]; float ww = g_cw[e];
        a0 = fmaf(ww, h0[s * 64 + lane], a0);
        a1 = fmaf(ww, h0[s * 64 + 32 + lane], a1);
        ax = fmaf(ww, x[s * 16 + cx], ax);
    }
    g_th1[w * 64 + lane]      = a0;
    g_th1[w * 64 + 32 + lane] = a1;
    if (lane < 16) g_tx1[w * 16 + lane] = ax;
}

__global__ void k_prop_xh2(const float* __restrict__ x, const float* __restrict__ h0) {
    int w = (blockIdx.x * blockDim.x + threadIdx.x) >> 5;
    if (w >= Nn) return;
    int lane = threadIdx.x & 31, cx = lane & 15;
    int beg = g_rowptr[w], end = g_rowptr[w + 1];
    float a0 = 0.f, a1 = 0.f, ax = 0.f;
    int e = beg;
    for (; e + 1 < end; e += 2) {
        int   s0 = g_csrc[e], s1 = g_csrc[e + 1];
        float w0 = g_cw[e],   w1 = g_cw[e + 1];
        a0 = fmaf(w0, g_th1[s0 * 64 + lane],      fmaf(w1, g_th1[s1 * 64 + lane],      a0));
        a1 = fmaf(w0, g_th1[s0 * 64 + 32 + lane], fmaf(w1, g_th1[s1 * 64 + 32 + lane], a1));
        ax = fmaf(w0, g_tx1[s0 * 16 + cx],        fmaf(w1, g_tx1[s1 * 16 + cx],        ax));
    }
    if (e < end) {
        int s = g_csrc[e]; float ww = g_cw[e];
        a0 = fmaf(ww, g_th1[s * 64 + lane], a0);
        a1 = fmaf(ww, g_th1[s * 64 + 32 + lane], a1);
        ax = fmaf(ww, g_tx1[s * 16 + cx], ax);
    }
    g_th2[w * 64 + lane]      = 2.f * a0 - h0[w * 64 + lane];
    g_th2[w * 64 + 32 + lane] = 2.f * a1 - h0[w * 64 + 32 + lane];
    if (lane < 16) g_tx2[w * 16 + lane] = 2.f * ax - x[w * 16 + lane];
}

__device__ __forceinline__ void prop64_core(const float* __restrict__ vin,
                                            const float* __restrict__ sub,
                                            float* __restrict__ vout,
                                            bool fuse) {
    int w = (blockIdx.x * blockDim.x + threadIdx.x) >> 5;
    if (w >= Nn) return;
    int lane = threadIdx.x & 31;
    int beg = g_rowptr[w], end = g_rowptr[w + 1];
    float a0 = 0.f, a1 = 0.f;
    int e = beg;
    for (; e + 1 < end; e += 2) {
        int   s0 = g_csrc[e], s1 = g_csrc[e + 1];
        float w0 = g_cw[e],   w1 = g_cw[e + 1];
        a0 = fmaf(w0, vin[s0 * 64 + lane],      fmaf(w1, vin[s1 * 64 + lane],      a0));
        a1 = fmaf(w0, vin[s0 * 64 + 32 + lane], fmaf(w1, vin[s1 * 64 + 32 + lane], a1));
    }
    if (e < end) {
        int s = g_csrc[e]; float ww = g_cw[e];
        a0 = fmaf(ww, vin[s * 64 + lane], a0);
        a1 = fmaf(ww, vin[s * 64 + 32 + lane], a1);
    }
    if (fuse) {
        a0 = 2.f * a0 - sub[w * 64 + lane];
        a1 = 2.f * a1 - sub[w * 64 + 32 + lane];
    }
    vout[w * 64 + lane]      = a0;
    vout[w * 64 + 32 + lane] = a1;
}

__global__ void k_prop_r1() { prop64_core(g_hr,  nullptr, g_tr1, false); }
__global__ void k_prop_r2() { prop64_core(g_tr1, g_hr,    g_tr2, true ); }

// ---------------- GEMM zr: [64 rows] x (192 h-K + 48 x-K) -> z, hr ------------
// 128 threads: g = tid>>6 (gate z|r), co = tid&63. 32 f32x2 row-pair accums.
// dynamic smem: sAh[192][68] + sAx[48][68]
__global__ void __launch_bounds__(128) k_gemm_zr(
        const float* __restrict__ x,  const float* __restrict__ h0,
        const float* __restrict__ Wx, const float* __restrict__ Wh,
        const float* __restrict__ bx, const float* __restrict__ bh) {
    extern __shared__ float smem[];
    float (*sAh)[68] = (float(*)[68])smem;
    float (*sAx)[68] = (float(*)[68])(smem + 192 * 68);
    int tid  = threadIdx.x;
    int row0 = blockIdx.x * GR;
    for (int i = tid; i < GR * 192; i += 128) {
        int r = i / 192, kk = i - r * 192;
        int row = min(row0 + r, Nn - 1);
        int c = kk & 63, seg = kk >> 6;
        float v = (seg == 0) ? h0[row * 64 + c]
                : (seg == 1) ? g_th1[row * 64 + c]
                             : g_th2[row * 64 + c];
        sAh[kk][r] = v;
    }
    for (int i = tid; i < GR * 48; i += 128) {
        int r = i / 48, kk = i - r * 48;
        int row = min(row0 + r, Nn - 1);
        int c = kk & 15, seg = kk >> 4;
        float v = (seg == 0) ? x[row * 16 + c]
                : (seg == 1) ? g_tx1[row * 16 + c]
                             : g_tx2[row * 16 + c];
        sAx[kk][r] = v;
    }
    __syncthreads();

    int g = tid >> 6, co = tid & 63;
    ull acc[32];
#pragma unroll
    for (int r = 0; r < 32; r++) acc[r] = 0ull;

    const float* Wgh = Wh + (g * 192) * 64 + co;
    for (int kk = 0; kk < 192; kk++) {
        float w = Wgh[kk * 64];
        ull w2 = pack2(w, w);
        const ulonglong2* ap = (const ulonglong2*)sAh[kk];
#pragma unroll
        for (int j = 0; j < 16; j++) {
            ulonglong2 a = ap[j];
            ffma2(acc[2 * j],     a.x, w2);
            ffma2(acc[2 * j + 1], a.y, w2);
        }
    }
    const float* Wgx = Wx + (g * 48) * 64 + co;
    for (int kk = 0; kk < 48; kk++) {
        float w = Wgx[kk * 64];
        ull w2 = pack2(w, w);
        const ulonglong2* ap = (const ulonglong2*)sAx[kk];
#pragma unroll
        for (int j = 0; j < 16; j++) {
            ulonglong2 a = ap[j];
            ffma2(acc[2 * j],     a.x, w2);
            ffma2(acc[2 * j + 1], a.y, w2);
        }
    }

    float b = bh[g * 64 + co] + bx[g * 64 + co];
#pragma unroll
    for (int p = 0; p < 32; p++) {
        float2 v = unpack2(acc[p]);
        int rowa = row0 + 2 * p, rowb = rowa + 1;
        float sa = sigmoid_ap(v.x + b);
        float sb = sigmoid_ap(v.y + b);
        if (g == 0) {
            if (rowa < Nn) g_z[rowa * 64 + co] = sa;
            if (rowb < Nn) g_z[rowb * 64 + co] = sb;
        } else {
            if (rowa < Nn) g_hr[rowa * 64 + co] = sa * h0[rowa * 64 + co];
            if (rowb < Nn) g_hr[rowb * 64 + co] = sb * h0[rowb * 64 + co];
        }
    }
}

// ---------------- GEMM til: -> htil, h (blend), + fused y = relu(h)@Wlin ------
// 128 threads: co = tid&63, rh = tid>>6 (rows [rh*32, rh*32+32) = 16 pairs)
__global__ void __launch_bounds__(128) k_gemm_til(
        const float* __restrict__ x,  const float* __restrict__ h0,
        const float* __restrict__ Wx, const float* __restrict__ Wh,
        const float* __restrict__ bx, const float* __restrict__ bh,
        const float* __restrict__ Wlin, const float* __restrict__ blin,
        float* __restrict__ hout, float* __restrict__ yout) {
    extern __shared__ float smem[];
    float (*sAh)[68] = (float(*)[68])smem;
    float (*sAx)[68] = (float(*)[68])(smem + 192 * 68);
    float* sH = smem + 240 * 68;   // [GR][65]
    int tid  = threadIdx.x;
    int row0 = blockIdx.x * GR;
    for (int i = tid; i < GR * 192; i += 128) {
        int r = i / 192, kk = i - r * 192;
        int row = min(row0 + r, Nn - 1);
        int c = kk & 63, seg = kk >> 6;
        float v = (seg == 0) ? g_hr[row * 64 + c]
                : (seg == 1) ? g_tr1[row * 64 + c]
                             : g_tr2[row * 64 + c];
        sAh[kk][r] = v;
    }
    for (int i = tid; i < GR * 48; i += 128) {
        int r = i / 48, kk = i - r * 48;
        int row = min(row0 + r, Nn - 1);
        int c = kk & 15, seg = kk >> 4;
        float v = (seg == 0) ? x[row * 16 + c]
                : (seg == 1) ? g_tx1[row * 16 + c]
                             : g_tx2[row * 16 + c];
        sAx[kk][r] = v;
    }
    __syncthreads();

    int co = tid & 63, rh = tid >> 6;
    ull acc[16];
#pragma unroll
    for (int r = 0; r < 16; r++) acc[r] = 0ull;

    const float* Wgh = Wh + (2 * 192) * 64 + co;
    for (int kk = 0; kk < 192; kk++) {
        float w = Wgh[kk * 64];
        ull w2 = pack2(w, w);
        const ulonglong2* ap = (const ulonglong2*)sAh[kk] + rh * 8;
#pragma unroll
        for (int j = 0; j < 8; j++) {
            ulonglong2 a = ap[j];
            ffma2(acc[2 * j],     a.x, w2);
            ffma2(acc[2 * j + 1], a.y, w2);
        }
    }
    const float* Wgx = Wx + (2 * 48) * 64 + co;
    for (int kk = 0; kk < 48; kk++) {
        float w = Wgx[kk * 64];
        ull w2 = pack2(w, w);
        const ulonglong2* ap = (const ulonglong2*)sAx[kk] + rh * 8;
#pragma unroll
        for (int j = 0; j < 8; j++) {
            ulonglong2 a = ap[j];
            ffma2(acc[2 * j],     a.x, w2);
            ffma2(acc[2 * j + 1], a.y, w2);
        }
    }

    float b = bh[128 + co] + bx[128 + co];
#pragma unroll
    for (int p = 0; p < 16; p++) {
        float2 v = unpack2(acc[p]);
        int lr = rh * 32 + 2 * p;
#pragma unroll
        for (int hh = 0; hh < 2; hh++) {
            float pre = ((hh == 0) ? v.x : v.y) + b;
            int row = row0 + lr + hh;
            float ht = tanh_ap(pre);
            float z, hv = 0.f;
            if (row < Nn) {
                z  = g_z[row * 64 + co];
                hv = z * h0[row * 64 + co] + (1.0f - z) * ht;
                hout[row * 64 + co] = hv;
            }
            sH[(lr + hh) * 65 + co] = fmaxf(hv, 0.f);
        }
    }
    __syncthreads();

    for (int i = tid; i < GR * 7; i += 128) {
        int r = i / 7, j = i - r * 7;
        int row = row0 + r;
        if (row >= Nn) continue;
        float s = blin[j];
#pragma unroll 16
        for (int c = 0; c < 64; c++) s = fmaf(sH[r * 65 + c], Wlin[c * 7 + j], s);
        yout[row * 7 + j] = s;
    }
}

// ---------------- launch ------------------------------------------------------
extern "C" void kernel_launch(void* const* d_in, const int* in_sizes, int n_in,
                              void* d_out, int out_size) {
    const float* x    = (const float*)d_in[0];
    const void*  ei   = d_in[1];
    const float* ew   = (const float*)d_in[2];
    const float* h0   = (const float*)d_in[3];
    const float* Wx   = (const float*)d_in[4];
    const float* Wh   = (const float*)d_in[5];
    const float* bx   = (const float*)d_in[6];
    const float* bh   = (const float*)d_in[7];
    const float* Wlin = (const float*)d_in[8];
    const float* blin = (const float*)d_in[9];
    float* out  = (float*)d_out;
    float* hout = out;
    float* yout = out + (size_t)Nn * 64;

    const int TB = 256;
    const int gW = (Nn * 32 + TB - 1) / TB;      // warp-per-node grids
    const int gG = (Nn + GR - 1) / GR;           // GEMM grids (782)

    const int smemZR  = 240 * 68 * 4;            // 65280 B
    const int smemTIL = 240 * 68 * 4 + GR * 65 * 4;  // 81920 B
    cudaFuncSetAttribute(k_gemm_zr,  cudaFuncAttributeMaxDynamicSharedMemorySize, smemZR);
    cudaFuncSetAttribute(k_gemm_til, cudaFuncAttributeMaxDynamicSharedMemorySize, smemTIL);

    k_init<<<PB, SBK>>>((const unsigned*)ei);
    k_pre <<<PB, SBK>>>(ei, ew);

    k_prop_xh1<<<gW, TB>>>(x, h0);
    k_prop_xh2<<<gW, TB>>>(x, h0);
    k_gemm_zr <<<gG, 128, smemZR>>>(x, h0, Wx, Wh, bx, bh);

    k_prop_r1 <<<gW, TB>>>();
    k_prop_r2 <<<gW, TB>>>();
    k_gemm_til<<<gG, 128, smemTIL>>>(x, h0, Wx, Wh, bx, bh, Wlin, blin, hout, yout);
}